// round 5
// baseline (speedup 1.0000x reference)
#include <cuda_runtime.h>

#define FD 128
#define TILE 128
#define NTHR 256
#define SP 132           // smem pitch (floats); 132*4 % 16 == 0 -> float4 aligned
#define MAXN 50048

// Scratch (device globals; no allocation allowed)
__device__ float g_fbuf[(size_t)MAXN * FD];   // x @ W_in2fac
__device__ float g_conv[(size_t)MAXN * FD];   // segment-sum accumulator

__device__ __forceinline__ float ssp_f(float x) {
    // softplus(x) - log(2), numerically stable
    float t = __expf(-fabsf(x));
    return fmaxf(x, 0.0f) + __logf(1.0f + t) - 0.6931471805599453f;
}

// Inner product accumulation over one 32-wide K chunk held in smem.
// sA: [k][m] (pitch SP), sB: [k][n] (pitch SP). Thread (tx,ty) owns rows ty*8.., cols tx*8..
__device__ __forceinline__ void mm_accum(const float* sA, const float* sB,
                                         int tx, int ty, float (&acc)[8][8]) {
#pragma unroll
    for (int k = 0; k < 32; ++k) {
        float4 a0 = *(const float4*)(sA + k * SP + ty * 8);
        float4 a1 = *(const float4*)(sA + k * SP + ty * 8 + 4);
        float4 b0 = *(const float4*)(sB + k * SP + tx * 8);
        float4 b1 = *(const float4*)(sB + k * SP + tx * 8 + 4);
        float a[8] = {a0.x, a0.y, a0.z, a0.w, a1.x, a1.y, a1.z, a1.w};
        float b[8] = {b0.x, b0.y, b0.z, b0.w, b1.x, b1.y, b1.z, b1.w};
#pragma unroll
        for (int r = 0; r < 8; ++r)
#pragma unroll
            for (int c = 0; c < 8; ++c)
                acc[r][c] = fmaf(a[r], b[c], acc[r][c]);
    }
}

// C[128,128] += A[row0:row0+128, 0:128] @ W[128,128]; rows >= nvalid treated as 0.
__device__ __forceinline__ void gemm_global_A(const float* __restrict__ A, int row0, int nvalid,
                                              const float* __restrict__ W,
                                              float (&acc)[8][8], float* sA, float* sB,
                                              int tid, int tx, int ty) {
    for (int kc = 0; kc < 4; ++kc) {
        __syncthreads();
        // Load A chunk transposed: sA[k][m]
#pragma unroll
        for (int i = 0; i < 16; ++i) {
            int idx = tid + i * NTHR;      // 0..4095
            int m = idx >> 5, k = idx & 31;
            float v = 0.0f;
            if (m < nvalid) v = A[(row0 + m) * FD + kc * 32 + k];
            sA[k * SP + m] = v;
        }
        // Load W chunk: sB[k][n]
#pragma unroll
        for (int i = 0; i < 16; ++i) {
            int idx = tid + i * NTHR;
            int k = idx >> 7, n = idx & 127;
            sB[k * SP + n] = W[(kc * 32 + k) * FD + n];
        }
        __syncthreads();
        mm_accum(sA, sB, tx, ty, acc);
    }
}

// C[128,128] += H @ W where H (128x128) is distributed in registers:
// thread (tx,ty) holds H[ty*8+r][tx*8+j] in h[r][j].
__device__ __forceinline__ void gemm_chain(const float (&h)[8][8],
                                           const float* __restrict__ W,
                                           float (&acc)[8][8], float* sA, float* sB,
                                           int tid, int tx, int ty) {
    for (int kc = 0; kc < 4; ++kc) {
        __syncthreads();   // previous chunk's compute must be done before overwrite
        if ((tx >> 2) == kc) {
            // this thread's 8 columns fall inside chunk kc: local k = (tx&3)*8 + j
#pragma unroll
            for (int j = 0; j < 8; ++j)
#pragma unroll
                for (int r = 0; r < 8; ++r)
                    sA[((tx & 3) * 8 + j) * SP + ty * 8 + r] = h[r][j];
        }
#pragma unroll
        for (int i = 0; i < 16; ++i) {
            int idx = tid + i * NTHR;
            int k = idx >> 7, n = idx & 127;
            sB[k * SP + n] = W[(kc * 32 + k) * FD + n];
        }
        __syncthreads();
        mm_accum(sA, sB, tx, ty, acc);
    }
}

__global__ void k_zero(int n4) {
    int i = blockIdx.x * blockDim.x + threadIdx.x;
    if (i < n4) ((float4*)g_conv)[i] = make_float4(0.f, 0.f, 0.f, 0.f);
}

__global__ __launch_bounds__(NTHR) void k_in2fac(const float* __restrict__ x,
                                                 const float* __restrict__ Wi, int N) {
    __shared__ __align__(16) float sA[32 * SP];
    __shared__ __align__(16) float sB[32 * SP];
    int tid = threadIdx.x, tx = tid & 15, ty = tid >> 4;
    int row0 = blockIdx.x * TILE;
    int nv = min(TILE, N - row0);
    float acc[8][8] = {};
    gemm_global_A(x, row0, nv, Wi, acc, sA, sB, tid, tx, ty);
#pragma unroll
    for (int r = 0; r < 8; ++r) {
        int row = row0 + ty * 8 + r;
        if (row < N) {
            float* dst = g_fbuf + (size_t)row * FD + tx * 8;
#pragma unroll
            for (int c = 0; c < 8; ++c) dst[c] = acc[r][c];
        }
    }
}

__global__ __launch_bounds__(NTHR) void k_edge(const float* __restrict__ dijk,
                                               const float* __restrict__ W1,
                                               const float* __restrict__ b1,
                                               const float* __restrict__ W2,
                                               const float* __restrict__ b2,
                                               const int* __restrict__ idx_j,
                                               const int* __restrict__ seg_i,
                                               int E) {
    __shared__ __align__(16) float sA[32 * SP];
    __shared__ __align__(16) float sB[32 * SP];
    int tid = threadIdx.x, tx = tid & 15, ty = tid >> 4;
    int e0 = blockIdx.x * TILE;
    int nv = min(TILE, E - e0);

    // h = ssp(dijk @ W1 + b1)
    float acc[8][8] = {};
    gemm_global_A(dijk, e0, nv, W1, acc, sA, sB, tid, tx, ty);
    float bias[8];
#pragma unroll
    for (int c = 0; c < 8; ++c) bias[c] = b1[tx * 8 + c];
    float h[8][8];
#pragma unroll
    for (int r = 0; r < 8; ++r)
#pragma unroll
        for (int c = 0; c < 8; ++c)
            h[r][c] = ssp_f(acc[r][c] + bias[c]);

    // w = ssp(h @ W2 + b2)   (seg_j is arange -> first segment_sum is identity)
    float acc2[8][8] = {};
    gemm_chain(h, W2, acc2, sA, sB, tid, tx, ty);
#pragma unroll
    for (int c = 0; c < 8; ++c) bias[c] = b2[tx * 8 + c];
#pragma unroll
    for (int r = 0; r < 8; ++r)
#pragma unroll
        for (int c = 0; c < 8; ++c)
            acc2[r][c] = ssp_f(acc2[r][c] + bias[c]);

    // wf = w * f[idx_j];  run-length-compressed segmented atomicAdd into conv[seg_i]
    int col0 = tx * 8;
    float accv[8];
    int cur = -1;
#pragma unroll
    for (int r = 0; r < 8; ++r) {
        int e = e0 + ty * 8 + r;
        if (e < E) {
            int j = idx_j[e];
            const float4* frow = (const float4*)(g_fbuf + (size_t)j * FD + col0);
            float4 f0 = frow[0], f1 = frow[1];
            float wf[8];
            wf[0] = acc2[r][0] * f0.x; wf[1] = acc2[r][1] * f0.y;
            wf[2] = acc2[r][2] * f0.z; wf[3] = acc2[r][3] * f0.w;
            wf[4] = acc2[r][4] * f1.x; wf[5] = acc2[r][5] * f1.y;
            wf[6] = acc2[r][6] * f1.z; wf[7] = acc2[r][7] * f1.w;
            int s = seg_i[e];
            if (s != cur) {
                if (cur >= 0) {
                    float* dst = g_conv + (size_t)cur * FD + col0;
#pragma unroll
                    for (int c = 0; c < 8; ++c) atomicAdd(dst + c, accv[c]);
                }
                cur = s;
#pragma unroll
                for (int c = 0; c < 8; ++c) accv[c] = wf[c];
            } else {
#pragma unroll
                for (int c = 0; c < 8; ++c) accv[c] += wf[c];
            }
        }
    }
    if (cur >= 0) {
        float* dst = g_conv + (size_t)cur * FD + col0;
#pragma unroll
        for (int c = 0; c < 8; ++c) atomicAdd(dst + c, accv[c]);
    }
}

__global__ __launch_bounds__(NTHR) void k_atom(const float* __restrict__ x,
                                               const float* __restrict__ Wf,
                                               const float* __restrict__ bf,
                                               const float* __restrict__ Wd,
                                               const float* __restrict__ bd,
                                               float* __restrict__ out,
                                               int N, int hasv) {
    __shared__ __align__(16) float sA[32 * SP];
    __shared__ __align__(16) float sB[32 * SP];
    int tid = threadIdx.x, tx = tid & 15, ty = tid >> 4;
    int row0 = blockIdx.x * TILE;
    int nv = min(TILE, N - row0);

    // c = ssp(conv @ W_fac2out + b_fac2out)
    float acc[8][8] = {};
    gemm_global_A(g_conv, row0, nv, Wf, acc, sA, sB, tid, tx, ty);
    float bias[8];
#pragma unroll
    for (int c = 0; c < 8; ++c) bias[c] = bf[tx * 8 + c];
    float h[8][8];
#pragma unroll
    for (int r = 0; r < 8; ++r)
#pragma unroll
        for (int c = 0; c < 8; ++c)
            h[r][c] = ssp_f(acc[r][c] + bias[c]);

    // v = c @ W_dense + b_dense;  y = x + v
    float acc2[8][8] = {};
    gemm_chain(h, Wd, acc2, sA, sB, tid, tx, ty);
#pragma unroll
    for (int c = 0; c < 8; ++c) bias[c] = bd[tx * 8 + c];

    int col0 = tx * 8;
#pragma unroll
    for (int r = 0; r < 8; ++r) {
        int row = row0 + ty * 8 + r;
        if (row < N) {
            const float* xr = x + (size_t)row * FD + col0;
            float* ydst = out + (size_t)row * FD + col0;
            float* vdst = out + (size_t)N * FD + (size_t)row * FD + col0;
#pragma unroll
            for (int c = 0; c < 8; ++c) {
                float v = acc2[r][c] + bias[c];
                ydst[c] = xr[c] + v;
                if (hasv) vdst[c] = v;
            }
        }
    }
}

extern "C" void kernel_launch(void* const* d_in, const int* in_sizes, int n_in,
                              void* d_out, int out_size) {
    const float* x    = (const float*)d_in[0];
    const float* dijk = (const float*)d_in[1];
    const int* idx_j  = (const int*)d_in[2];
    const int* seg_i  = (const int*)d_in[3];
    // Skip seg_j (and seg_i_sum if present) -- find first 128x128 weight tensor.
    int wb = 4;
    while (wb < n_in && in_sizes[wb] != FD * FD) ++wb;
    const float* W1 = (const float*)d_in[wb + 0];
    const float* b1 = (const float*)d_in[wb + 1];
    const float* W2 = (const float*)d_in[wb + 2];
    const float* b2 = (const float*)d_in[wb + 3];
    const float* Wi = (const float*)d_in[wb + 4];
    const float* Wf = (const float*)d_in[wb + 5];
    const float* bf = (const float*)d_in[wb + 6];
    const float* Wd = (const float*)d_in[wb + 7];
    const float* bd = (const float*)d_in[wb + 8];

    int N = in_sizes[0] / FD;
    int E = in_sizes[1] / FD;
    float* out = (float*)d_out;
    int hasv = (out_size >= 2 * N * FD) ? 1 : 0;

    int nblkN = (N + TILE - 1) / TILE;
    int nblkE = (E + TILE - 1) / TILE;
    int n4 = (N * FD) / 4;

    k_zero<<<(n4 + 255) / 256, 256>>>(n4);
    k_in2fac<<<nblkN, NTHR>>>(x, Wi, N);
    k_edge<<<nblkE, NTHR>>>(dijk, W1, b1, W2, b2, idx_j, seg_i, E);
    k_atom<<<nblkN, NTHR>>>(x, Wf, bf, Wd, bd, out, N, hasv);
}

// round 6
// speedup vs baseline: 1.0002x; 1.0002x over previous
#include <cuda_runtime.h>

#define FD 128
#define TILE 128
#define NTHR 256
#define SP 132           // smem pitch (floats); 132*4 % 16 == 0 -> float4 aligned
#define MAXN 50048

// Scratch (device globals; no allocation allowed)
__device__ float g_fbuf[(size_t)MAXN * FD];   // x @ W_in2fac
__device__ float g_conv[(size_t)MAXN * FD];   // segment-sum accumulator

__device__ __forceinline__ float ssp_f(float x) {
    // softplus(x) - log(2), numerically stable
    float t = __expf(-fabsf(x));
    return fmaxf(x, 0.0f) + __logf(1.0f + t) - 0.6931471805599453f;
}

// Inner product accumulation over one 32-wide K chunk held in smem.
// sA: [k][m] (pitch SP), sB: [k][n] (pitch SP). Thread (tx,ty) owns rows ty*8.., cols tx*8..
__device__ __forceinline__ void mm_accum(const float* sA, const float* sB,
                                         int tx, int ty, float (&acc)[8][8]) {
#pragma unroll
    for (int k = 0; k < 32; ++k) {
        float4 a0 = *(const float4*)(sA + k * SP + ty * 8);
        float4 a1 = *(const float4*)(sA + k * SP + ty * 8 + 4);
        float4 b0 = *(const float4*)(sB + k * SP + tx * 8);
        float4 b1 = *(const float4*)(sB + k * SP + tx * 8 + 4);
        float a[8] = {a0.x, a0.y, a0.z, a0.w, a1.x, a1.y, a1.z, a1.w};
        float b[8] = {b0.x, b0.y, b0.z, b0.w, b1.x, b1.y, b1.z, b1.w};
#pragma unroll
        for (int r = 0; r < 8; ++r)
#pragma unroll
            for (int c = 0; c < 8; ++c)
                acc[r][c] = fmaf(a[r], b[c], acc[r][c]);
    }
}

// C[128,128] += A[row0:row0+128, 0:128] @ W[128,128]; rows >= nvalid treated as 0.
__device__ __forceinline__ void gemm_global_A(const float* __restrict__ A, int row0, int nvalid,
                                              const float* __restrict__ W,
                                              float (&acc)[8][8], float* sA, float* sB,
                                              int tid, int tx, int ty) {
    for (int kc = 0; kc < 4; ++kc) {
        __syncthreads();
        // Load A chunk transposed: sA[k][m]
#pragma unroll
        for (int i = 0; i < 16; ++i) {
            int idx = tid + i * NTHR;      // 0..4095
            int m = idx >> 5, k = idx & 31;
            float v = 0.0f;
            if (m < nvalid) v = A[(row0 + m) * FD + kc * 32 + k];
            sA[k * SP + m] = v;
        }
        // Load W chunk: sB[k][n]
#pragma unroll
        for (int i = 0; i < 16; ++i) {
            int idx = tid + i * NTHR;
            int k = idx >> 7, n = idx & 127;
            sB[k * SP + n] = W[(kc * 32 + k) * FD + n];
        }
        __syncthreads();
        mm_accum(sA, sB, tx, ty, acc);
    }
}

// C[128,128] += H @ W where H (128x128) is distributed in registers:
// thread (tx,ty) holds H[ty*8+r][tx*8+j] in h[r][j].
__device__ __forceinline__ void gemm_chain(const float (&h)[8][8],
                                           const float* __restrict__ W,
                                           float (&acc)[8][8], float* sA, float* sB,
                                           int tid, int tx, int ty) {
    for (int kc = 0; kc < 4; ++kc) {
        __syncthreads();   // previous chunk's compute must be done before overwrite
        if ((tx >> 2) == kc) {
            // this thread's 8 columns fall inside chunk kc: local k = (tx&3)*8 + j
#pragma unroll
            for (int j = 0; j < 8; ++j)
#pragma unroll
                for (int r = 0; r < 8; ++r)
                    sA[((tx & 3) * 8 + j) * SP + ty * 8 + r] = h[r][j];
        }
#pragma unroll
        for (int i = 0; i < 16; ++i) {
            int idx = tid + i * NTHR;
            int k = idx >> 7, n = idx & 127;
            sB[k * SP + n] = W[(kc * 32 + k) * FD + n];
        }
        __syncthreads();
        mm_accum(sA, sB, tx, ty, acc);
    }
}

__global__ void k_zero(int n4) {
    int i = blockIdx.x * blockDim.x + threadIdx.x;
    if (i < n4) ((float4*)g_conv)[i] = make_float4(0.f, 0.f, 0.f, 0.f);
}

__global__ __launch_bounds__(NTHR) void k_in2fac(const float* __restrict__ x,
                                                 const float* __restrict__ Wi, int N) {
    __shared__ __align__(16) float sA[32 * SP];
    __shared__ __align__(16) float sB[32 * SP];
    int tid = threadIdx.x, tx = tid & 15, ty = tid >> 4;
    int row0 = blockIdx.x * TILE;
    int nv = min(TILE, N - row0);
    float acc[8][8] = {};
    gemm_global_A(x, row0, nv, Wi, acc, sA, sB, tid, tx, ty);
#pragma unroll
    for (int r = 0; r < 8; ++r) {
        int row = row0 + ty * 8 + r;
        if (row < N) {
            float* dst = g_fbuf + (size_t)row * FD + tx * 8;
#pragma unroll
            for (int c = 0; c < 8; ++c) dst[c] = acc[r][c];
        }
    }
}

__global__ __launch_bounds__(NTHR) void k_edge(const float* __restrict__ dijk,
                                               const float* __restrict__ W1,
                                               const float* __restrict__ b1,
                                               const float* __restrict__ W2,
                                               const float* __restrict__ b2,
                                               const int* __restrict__ idx_j,
                                               const int* __restrict__ seg_i,
                                               int E) {
    __shared__ __align__(16) float sA[32 * SP];
    __shared__ __align__(16) float sB[32 * SP];
    int tid = threadIdx.x, tx = tid & 15, ty = tid >> 4;
    int e0 = blockIdx.x * TILE;
    int nv = min(TILE, E - e0);

    // h = ssp(dijk @ W1 + b1)
    float acc[8][8] = {};
    gemm_global_A(dijk, e0, nv, W1, acc, sA, sB, tid, tx, ty);
    float bias[8];
#pragma unroll
    for (int c = 0; c < 8; ++c) bias[c] = b1[tx * 8 + c];
    float h[8][8];
#pragma unroll
    for (int r = 0; r < 8; ++r)
#pragma unroll
        for (int c = 0; c < 8; ++c)
            h[r][c] = ssp_f(acc[r][c] + bias[c]);

    // w = ssp(h @ W2 + b2)   (seg_j is arange -> first segment_sum is identity)
    float acc2[8][8] = {};
    gemm_chain(h, W2, acc2, sA, sB, tid, tx, ty);
#pragma unroll
    for (int c = 0; c < 8; ++c) bias[c] = b2[tx * 8 + c];
#pragma unroll
    for (int r = 0; r < 8; ++r)
#pragma unroll
        for (int c = 0; c < 8; ++c)
            acc2[r][c] = ssp_f(acc2[r][c] + bias[c]);

    // wf = w * f[idx_j];  run-length-compressed segmented atomicAdd into conv[seg_i]
    int col0 = tx * 8;
    float accv[8];
    int cur = -1;
#pragma unroll
    for (int r = 0; r < 8; ++r) {
        int e = e0 + ty * 8 + r;
        if (e < E) {
            int j = idx_j[e];
            const float4* frow = (const float4*)(g_fbuf + (size_t)j * FD + col0);
            float4 f0 = frow[0], f1 = frow[1];
            float wf[8];
            wf[0] = acc2[r][0] * f0.x; wf[1] = acc2[r][1] * f0.y;
            wf[2] = acc2[r][2] * f0.z; wf[3] = acc2[r][3] * f0.w;
            wf[4] = acc2[r][4] * f1.x; wf[5] = acc2[r][5] * f1.y;
            wf[6] = acc2[r][6] * f1.z; wf[7] = acc2[r][7] * f1.w;
            int s = seg_i[e];
            if (s != cur) {
                if (cur >= 0) {
                    float* dst = g_conv + (size_t)cur * FD + col0;
#pragma unroll
                    for (int c = 0; c < 8; ++c) atomicAdd(dst + c, accv[c]);
                }
                cur = s;
#pragma unroll
                for (int c = 0; c < 8; ++c) accv[c] = wf[c];
            } else {
#pragma unroll
                for (int c = 0; c < 8; ++c) accv[c] += wf[c];
            }
        }
    }
    if (cur >= 0) {
        float* dst = g_conv + (size_t)cur * FD + col0;
#pragma unroll
        for (int c = 0; c < 8; ++c) atomicAdd(dst + c, accv[c]);
    }
}

__global__ __launch_bounds__(NTHR) void k_atom(const float* __restrict__ x,
                                               const float* __restrict__ Wf,
                                               const float* __restrict__ bf,
                                               const float* __restrict__ Wd,
                                               const float* __restrict__ bd,
                                               float* __restrict__ out,
                                               int N, int hasv) {
    __shared__ __align__(16) float sA[32 * SP];
    __shared__ __align__(16) float sB[32 * SP];
    int tid = threadIdx.x, tx = tid & 15, ty = tid >> 4;
    int row0 = blockIdx.x * TILE;
    int nv = min(TILE, N - row0);

    // c = ssp(conv @ W_fac2out + b_fac2out)
    float acc[8][8] = {};
    gemm_global_A(g_conv, row0, nv, Wf, acc, sA, sB, tid, tx, ty);
    float bias[8];
#pragma unroll
    for (int c = 0; c < 8; ++c) bias[c] = bf[tx * 8 + c];
    float h[8][8];
#pragma unroll
    for (int r = 0; r < 8; ++r)
#pragma unroll
        for (int c = 0; c < 8; ++c)
            h[r][c] = ssp_f(acc[r][c] + bias[c]);

    // v = c @ W_dense + b_dense;  y = x + v
    float acc2[8][8] = {};
    gemm_chain(h, Wd, acc2, sA, sB, tid, tx, ty);
#pragma unroll
    for (int c = 0; c < 8; ++c) bias[c] = bd[tx * 8 + c];

    int col0 = tx * 8;
#pragma unroll
    for (int r = 0; r < 8; ++r) {
        int row = row0 + ty * 8 + r;
        if (row < N) {
            const float* xr = x + (size_t)row * FD + col0;
            float* ydst = out + (size_t)row * FD + col0;
            float* vdst = out + (size_t)N * FD + (size_t)row * FD + col0;
#pragma unroll
            for (int c = 0; c < 8; ++c) {
                float v = acc2[r][c] + bias[c];
                ydst[c] = xr[c] + v;
                if (hasv) vdst[c] = v;
            }
        }
    }
}

extern "C" void kernel_launch(void* const* d_in, const int* in_sizes, int n_in,
                              void* d_out, int out_size) {
    const float* x    = (const float*)d_in[0];
    const float* dijk = (const float*)d_in[1];
    const int* idx_j  = (const int*)d_in[2];
    const int* seg_i  = (const int*)d_in[3];
    // Skip seg_j (and seg_i_sum if present) -- find first 128x128 weight tensor.
    int wb = 4;
    while (wb < n_in && in_sizes[wb] != FD * FD) ++wb;
    const float* W1 = (const float*)d_in[wb + 0];
    const float* b1 = (const float*)d_in[wb + 1];
    const float* W2 = (const float*)d_in[wb + 2];
    const float* b2 = (const float*)d_in[wb + 3];
    const float* Wi = (const float*)d_in[wb + 4];
    const float* Wf = (const float*)d_in[wb + 5];
    const float* bf = (const float*)d_in[wb + 6];
    const float* Wd = (const float*)d_in[wb + 7];
    const float* bd = (const float*)d_in[wb + 8];

    int N = in_sizes[0] / FD;
    int E = in_sizes[1] / FD;
    float* out = (float*)d_out;
    int hasv = (out_size >= 2 * N * FD) ? 1 : 0;

    int nblkN = (N + TILE - 1) / TILE;
    int nblkE = (E + TILE - 1) / TILE;
    int n4 = (N * FD) / 4;

    k_zero<<<(n4 + 255) / 256, 256>>>(n4);
    k_in2fac<<<nblkN, NTHR>>>(x, Wi, N);
    k_edge<<<nblkE, NTHR>>>(dijk, W1, b1, W2, b2, idx_j, seg_i, E);
    k_atom<<<nblkN, NTHR>>>(x, Wf, bf, Wd, bd, out, N, hasv);
}